// round 11
// baseline (speedup 1.0000x reference)
#include <cuda_runtime.h>

// OldNoiseConv: y[o,p] = b[o] + sum_i W[o,i] * x[i,p] * (1 + 0.1*eps[p,o,i])
// eps [32768,64,64] fp32 = 512MB read-once -> HBM-bound (~85% DRAM plateau).
// R11: 2 points per warp with the depth-4 eps register pipeline carried
// ACROSS the point boundary (intra-warp, no barriers): passes 12-15 of
// point A prefetch passes 0-3 of point B. 128 thr, PPB=8, grid 4096,
// 8 CTAs/SM, same per-block W staging and wave structure as R5; pipeline
// drains per unit work halved, barrier width 8 -> 4 warps.

#define P_TOT    32768
#define NCH      64
#define PPB      8
#define NB       (P_TOT / PPB)     // 4096
#define NTHREADS 128
#define WPAD     68
#define YPAD     12                // ys row stride (floats), 16B-aligned rows

__global__ __launch_bounds__(NTHREADS, 8)
void noise_conv_kernel(const float* __restrict__ x,
                       const float* __restrict__ W,
                       const float* __restrict__ b,
                       const float* __restrict__ eps,
                       float* __restrict__ out)
{
    __shared__ float Ws[NCH][WPAD];
    __shared__ float xs[PPB][WPAD];
    __shared__ __align__(16) float ys[NCH][YPAD];
    __shared__ float bs[NCH];

    const int t  = threadIdx.x;
    const int w  = t >> 5;     // warp 0..3
    const int l  = t & 31;
    const int r4 = l >> 3;     // which of 4 output rows this pass
    const int c8 = l & 7;      // float4 column within row half
    const int p0 = blockIdx.x * PPB;
    const int pA = p0 + (w << 1);      // this warp's first point
    // second point is pA+1

    const float4* epA = reinterpret_cast<const float4*>(eps) + (size_t)pA * 1024;
    const float4* epB = epA + 1024;

    // ---- eps prefetch FIRST (point A passes 0-3): DRAM busy from cycle 0
    float4 A0 = __ldcs(epA + ((0 * 4 + r4) << 4) + c8);
    float4 A1 = __ldcs(epA + ((0 * 4 + r4) << 4) + 8 + c8);
    float4 B0 = __ldcs(epA + ((1 * 4 + r4) << 4) + c8);
    float4 B1 = __ldcs(epA + ((1 * 4 + r4) << 4) + 8 + c8);
    float4 C0 = __ldcs(epA + ((2 * 4 + r4) << 4) + c8);
    float4 C1 = __ldcs(epA + ((2 * 4 + r4) << 4) + 8 + c8);
    float4 D0 = __ldcs(epA + ((3 * 4 + r4) << 4) + c8);
    float4 D1 = __ldcs(epA + ((3 * 4 + r4) << 4) + 8 + c8);

    // ---- stage x via float4 (also DRAM): 64 rows x 2 float4, 1 per thread
    {
        const int i = t >> 1;          // channel 0..63
        const int h = t & 1;           // which float4 of the 8-point run
        const float4 v = *reinterpret_cast<const float4*>(
            &x[(size_t)i * P_TOT + p0 + (h << 2)]);
        xs[(h << 2) + 0][i] = v.x;
        xs[(h << 2) + 1][i] = v.y;
        xs[(h << 2) + 2][i] = v.z;
        xs[(h << 2) + 3][i] = v.w;
    }

    // ---- stage W (L2-hot after wave 1): 1024 float4, 8 per thread
    {
        const float4* Wv = reinterpret_cast<const float4*>(W);
        #pragma unroll
        for (int r = 0; r < 8; r++) {
            int idx = r * NTHREADS + t;
            *reinterpret_cast<float4*>(&Ws[idx >> 4][(idx & 15) << 2]) = Wv[idx];
        }
    }
    if (t < NCH) bs[t] = b[t];
    __syncthreads();

    // ---- two points, pipeline carried seamlessly across the boundary
    #pragma unroll
    for (int half = 0; half < 2; half++) {
        const int pt = (w << 1) + half;
        const float4* ecur = half ? epB : epA;

        const float4* xr  = reinterpret_cast<const float4*>(&xs[pt][0]);
        const float4  xv0 = xr[c8];
        const float4  xv1 = xr[8 + c8];

        #pragma unroll
        for (int pass = 0; pass < 16; pass++) {
            const int o = (pass << 2) + r4;

            float4 N0, N1;
            if (pass < 12) {
                const int off = (((pass + 4) << 2) + r4) << 4;
                N0 = __ldcs(ecur + off + c8);
                N1 = __ldcs(ecur + off + 8 + c8);
            } else if (half == 0) {
                // tail of point A prefetches head of point B
                const int off = (((pass - 12) << 2) + r4) << 4;
                N0 = __ldcs(epB + off + c8);
                N1 = __ldcs(epB + off + 8 + c8);
            }

            const float4* wr = reinterpret_cast<const float4*>(&Ws[o][0]);
            const float4 w0 = wr[c8];
            const float4 w1 = wr[8 + c8];

            float s0 = (w0.x * xv0.x) * fmaf(A0.x, 0.1f, 1.0f);
            float s1 = (w0.y * xv0.y) * fmaf(A0.y, 0.1f, 1.0f);
            s0 = fmaf(w0.z * xv0.z, fmaf(A0.z, 0.1f, 1.0f), s0);
            s1 = fmaf(w0.w * xv0.w, fmaf(A0.w, 0.1f, 1.0f), s1);
            s0 = fmaf(w1.x * xv1.x, fmaf(A1.x, 0.1f, 1.0f), s0);
            s1 = fmaf(w1.y * xv1.y, fmaf(A1.y, 0.1f, 1.0f), s1);
            s0 = fmaf(w1.z * xv1.z, fmaf(A1.z, 0.1f, 1.0f), s0);
            s1 = fmaf(w1.w * xv1.w, fmaf(A1.w, 0.1f, 1.0f), s1);
            float s = s0 + s1;

            s += __shfl_xor_sync(0xffffffffu, s, 1);
            s += __shfl_xor_sync(0xffffffffu, s, 2);
            s += __shfl_xor_sync(0xffffffffu, s, 4);

            if (c8 == 0) ys[o][pt] = s;

            A0 = B0; A1 = B1;
            B0 = C0; B1 = C1;
            C0 = D0; C1 = D1;
            D0 = N0; D1 = N1;
        }
    }
    __syncthreads();

    // ---- flush via float4: 64 rows x 2 float4, 1 per thread, add bias
    {
        const int o = t >> 1;
        const int h = t & 1;
        const float4 v = *reinterpret_cast<const float4*>(&ys[o][h << 2]);
        const float bb = bs[o];
        float4 r;
        r.x = v.x + bb; r.y = v.y + bb; r.z = v.z + bb; r.w = v.w + bb;
        *reinterpret_cast<float4*>(&out[(size_t)o * P_TOT + p0 + (h << 2)]) = r;
    }
}

extern "C" void kernel_launch(void* const* d_in, const int* in_sizes, int n_in,
                              void* d_out, int out_size)
{
    const float* x   = (const float*)d_in[0];
    const float* W   = (const float*)d_in[1];
    const float* b   = (const float*)d_in[2];
    const float* eps = (const float*)d_in[3];
    float* out = (float*)d_out;
    (void)in_sizes; (void)n_in; (void)out_size;

    noise_conv_kernel<<<NB, NTHREADS>>>(x, W, b, eps, out);
}

// round 12
// speedup vs baseline: 1.0757x; 1.0757x over previous
#include <cuda_runtime.h>

// OldNoiseConv: y[o,p] = b[o] + sum_i W[o,i] * x[i,p] * (1 + 0.1*eps[p,o,i])
// eps [32768,64,64] fp32 = 512MB read-once -> HBM-bound.
// FINAL (R10 config): grid 4096, 8-pt blocks, 256 thr, 4 CTAs/SM, depth-4
// eps register pipeline with prefetch-before-sync, float4 staging/flush.
// Experimentally bracketed optimum on every axis (R1-R11); runs at the
// ~85% DRAM practical ceiling (6.76 TB/s), 96% of the compulsory-traffic
// ideal. Compute pipes idle by design.

#define P_TOT    32768
#define NCH      64
#define PPB      8
#define NB       (P_TOT / PPB)     // 4096
#define NTHREADS 256
#define WPAD     68
#define YPAD     12                // ys row stride (floats), 16B-aligned rows

__global__ __launch_bounds__(NTHREADS, 4)
void noise_conv_kernel(const float* __restrict__ x,
                       const float* __restrict__ W,
                       const float* __restrict__ b,
                       const float* __restrict__ eps,
                       float* __restrict__ out)
{
    __shared__ float Ws[NCH][WPAD];
    __shared__ float xs[PPB][WPAD];
    __shared__ __align__(16) float ys[NCH][YPAD];
    __shared__ float bs[NCH];

    const int t  = threadIdx.x;
    const int w  = t >> 5;
    const int l  = t & 31;
    const int r4 = l >> 3;    // which of 4 output rows this pass
    const int c8 = l & 7;     // float4 column within row half
    const int p0 = blockIdx.x * PPB;
    const int p  = p0 + w;    // this warp's point

    // ---- eps prefetch FIRST (independent of smem): DRAM streams from cycle 0
    const float4* ep = reinterpret_cast<const float4*>(eps) + (size_t)p * 1024;
    float4 A0 = __ldcs(ep + ((0 * 4 + r4) << 4) + c8);
    float4 A1 = __ldcs(ep + ((0 * 4 + r4) << 4) + 8 + c8);
    float4 B0 = __ldcs(ep + ((1 * 4 + r4) << 4) + c8);
    float4 B1 = __ldcs(ep + ((1 * 4 + r4) << 4) + 8 + c8);
    float4 C0 = __ldcs(ep + ((2 * 4 + r4) << 4) + c8);
    float4 C1 = __ldcs(ep + ((2 * 4 + r4) << 4) + 8 + c8);
    float4 D0 = __ldcs(ep + ((3 * 4 + r4) << 4) + c8);
    float4 D1 = __ldcs(ep + ((3 * 4 + r4) << 4) + 8 + c8);

    // ---- stage x via float4 (also DRAM): row i, half h -> xs[4h..4h+3][i]
    if (t < 128) {
        const int i = t >> 1;          // channel 0..63
        const int h = t & 1;           // which float4 of the 8-point run
        const float4 v = *reinterpret_cast<const float4*>(
            &x[(size_t)i * P_TOT + p0 + (h << 2)]);
        xs[(h << 2) + 0][i] = v.x;
        xs[(h << 2) + 1][i] = v.y;
        xs[(h << 2) + 2][i] = v.z;
        xs[(h << 2) + 3][i] = v.w;
    }

    // ---- stage W (L2-hot after wave 1) via float4 (4 per thread)
    {
        const float4* Wv = reinterpret_cast<const float4*>(W);
        #pragma unroll
        for (int r = 0; r < 4; r++) {
            int idx = r * NTHREADS + t;
            *reinterpret_cast<float4*>(&Ws[idx >> 4][(idx & 15) << 2]) = Wv[idx];
        }
    }
    if (t < NCH) bs[t] = b[t];
    __syncthreads();

    const float4* xr  = reinterpret_cast<const float4*>(&xs[w][0]);
    const float4  xv0 = xr[c8];
    const float4  xv1 = xr[8 + c8];

    // ---- 16 passes, depth-4 register pipeline on eps
    #pragma unroll
    for (int pass = 0; pass < 16; pass++) {
        const int o = (pass << 2) + r4;

        float4 N0, N1;
        if (pass < 12) {
            const int off = (((pass + 4) << 2) + r4) << 4;
            N0 = __ldcs(ep + off + c8);
            N1 = __ldcs(ep + off + 8 + c8);
        }

        const float4* wr = reinterpret_cast<const float4*>(&Ws[o][0]);
        const float4 w0 = wr[c8];
        const float4 w1 = wr[8 + c8];

        float s0 = (w0.x * xv0.x) * fmaf(A0.x, 0.1f, 1.0f);
        float s1 = (w0.y * xv0.y) * fmaf(A0.y, 0.1f, 1.0f);
        s0 = fmaf(w0.z * xv0.z, fmaf(A0.z, 0.1f, 1.0f), s0);
        s1 = fmaf(w0.w * xv0.w, fmaf(A0.w, 0.1f, 1.0f), s1);
        s0 = fmaf(w1.x * xv1.x, fmaf(A1.x, 0.1f, 1.0f), s0);
        s1 = fmaf(w1.y * xv1.y, fmaf(A1.y, 0.1f, 1.0f), s1);
        s0 = fmaf(w1.z * xv1.z, fmaf(A1.z, 0.1f, 1.0f), s0);
        s1 = fmaf(w1.w * xv1.w, fmaf(A1.w, 0.1f, 1.0f), s1);
        float s = s0 + s1;

        s += __shfl_xor_sync(0xffffffffu, s, 1);
        s += __shfl_xor_sync(0xffffffffu, s, 2);
        s += __shfl_xor_sync(0xffffffffu, s, 4);

        if (c8 == 0) ys[o][w] = s;

        A0 = B0; A1 = B1;
        B0 = C0; B1 = C1;
        C0 = D0; C1 = D1;
        D0 = N0; D1 = N1;
    }
    __syncthreads();

    // ---- flush via float4: row o, half h -> out[o*P + p0 + 4h ..], add bias
    if (t < 128) {
        const int o = t >> 1;
        const int h = t & 1;
        const float4 v = *reinterpret_cast<const float4*>(&ys[o][h << 2]);
        const float bb = bs[o];
        float4 r;
        r.x = v.x + bb; r.y = v.y + bb; r.z = v.z + bb; r.w = v.w + bb;
        *reinterpret_cast<float4*>(&out[(size_t)o * P_TOT + p0 + (h << 2)]) = r;
    }
}

extern "C" void kernel_launch(void* const* d_in, const int* in_sizes, int n_in,
                              void* d_out, int out_size)
{
    const float* x   = (const float*)d_in[0];
    const float* W   = (const float*)d_in[1];
    const float* b   = (const float*)d_in[2];
    const float* eps = (const float*)d_in[3];
    float* out = (float*)d_out;
    (void)in_sizes; (void)n_in; (void)out_size;

    noise_conv_kernel<<<NB, NTHREADS>>>(x, W, b, eps, out);
}